// round 5
// baseline (speedup 1.0000x reference)
#include <cuda_runtime.h>
#include <stdint.h>

#define N        100800
#define NC       80
#define STRIDE   85
#define MAX_NMS  4096
#define MAX_DET  1000
#define CAP      16384
#define NBUCKET  65536
#define CONF_T   0.4f
#define IOU_T    0.45f
#define MAX_WH   7680.0f

// ---------------- scratch (static __device__, allocation-free) ----------------
__device__ unsigned int        g_key[N];
__device__ unsigned int        g_hist[NBUCKET];
__device__ unsigned int        g_cutoff;
__device__ unsigned int        g_count;
__device__ unsigned long long  g_cand[CAP];
__device__ float4              g_obox[MAX_NMS];   // class-offset xyxy
__device__ float               g_area[MAX_NMS];
__device__ float4              g_bbox[MAX_NMS];   // plain xyxy (output)
__device__ float               g_score[MAX_NMS];
__device__ float               g_clsf[MAX_NMS];
__device__ unsigned long long  g_remv[64];
__device__ unsigned long long  g_mask[MAX_NMS * 64];

// ---------------- K0: zero scratch ----------------
__global__ void k_zero() {
    int i = blockIdx.x * blockDim.x + threadIdx.x;
    if (i < NBUCKET) g_hist[i] = 0u;
    if (i == 0)      g_count = 0u;
    if (i < 64)      g_remv[i] = 0ULL;
}

// ---------------- K1: per-anchor conf + histogram ----------------
__global__ void k_scores(const float* __restrict__ pred) {
    int i = blockIdx.x * blockDim.x + threadIdx.x;
    if (i >= N) return;
    const float* r = pred + (size_t)i * STRIDE;
    float obj = r[4];
    float best = -1.0f;
#pragma unroll 8
    for (int c = 0; c < NC; c++) {
        float p = __fmul_rn(r[5 + c], obj);
        if (p > best) best = p;
    }
    unsigned int key = 0u;
    if (best > CONF_T) key = __float_as_uint(best);   // positive -> monotone bits
    g_key[i] = key;
    if (key) atomicAdd(&g_hist[key >> 16], 1u);
}

// ---------------- K2: find cutoff bucket (suffix count >= MAX_NMS) ----------------
__global__ void k_cutoff() {
    __shared__ unsigned int s[1024];
    __shared__ int best;
    int t = threadIdx.x;
    unsigned int sum = 0;
    int base = t * 64;
#pragma unroll 8
    for (int k = 0; k < 64; k++) sum += g_hist[base + k];
    s[t] = sum;
    __syncthreads();
    // inclusive suffix scan (Hillis-Steele)
    for (int off = 1; off < 1024; off <<= 1) {
        unsigned int v = (t + off < 1024) ? s[t + off] : 0u;
        __syncthreads();
        s[t] += v;
        __syncthreads();
    }
    if (t == 0) best = -1;
    __syncthreads();
    if (s[t] >= (unsigned)MAX_NMS && (t == 1023 || s[t + 1] < (unsigned)MAX_NMS))
        best = t;
    __syncthreads();
    if (t == 0) {
        if (best < 0) {
            g_cutoff = 0u;   // fewer than MAX_NMS candidates: take everything
        } else {
            unsigned int running = (best < 1023) ? s[best + 1] : 0u;
            unsigned int cut = (unsigned)(best * 64);
            for (int b = best * 64 + 63; b >= best * 64; b--) {
                running += g_hist[b];
                if (running >= (unsigned)MAX_NMS) { cut = (unsigned)b; break; }
            }
            g_cutoff = cut;
        }
    }
}

// ---------------- K3: gather candidates >= cutoff ----------------
__global__ void k_gather() {
    int i = blockIdx.x * blockDim.x + threadIdx.x;
    if (i >= N) return;
    unsigned int key = g_key[i];
    if (key && (key >> 16) >= g_cutoff) {
        unsigned int p = atomicAdd(&g_count, 1u);
        if (p < CAP)
            g_cand[p] = ((unsigned long long)key << 32) | (unsigned int)(~(unsigned int)i);
    }
}

// ---------------- K4: bitonic sort (desc) + prepare top MAX_NMS ----------------
__global__ void k_sort(const float* __restrict__ pred) {
    extern __shared__ unsigned long long s[];
    int tid = threadIdx.x;
    unsigned int cnt = g_count;
    if (cnt > CAP) cnt = CAP;
    for (int j = tid; j < CAP; j += 1024) s[j] = (j < (int)cnt) ? g_cand[j] : 0ULL;
    __syncthreads();
    for (int k = 2; k <= CAP; k <<= 1) {
        for (int j = k >> 1; j > 0; j >>= 1) {
            for (int t = tid; t < CAP; t += 1024) {
                int ixj = t ^ j;
                if (ixj > t) {
                    unsigned long long a = s[t], b = s[ixj];
                    bool sw = ((t & k) == 0) ? (a < b) : (a > b);   // descending
                    if (sw) { s[t] = b; s[ixj] = a; }
                }
            }
            __syncthreads();
        }
    }
    // decode top MAX_NMS ranks
    for (int r = tid; r < MAX_NMS; r += 1024) {
        unsigned long long key = s[r];
        unsigned int kb = (unsigned int)(key >> 32);
        if (kb == 0u) {
            atomicOr(&g_remv[r >> 6], 1ULL << (r & 63));
            g_obox[r] = make_float4(1e30f, 1e30f, 1e30f, 1e30f);
            g_area[r] = 0.0f;
            g_bbox[r] = make_float4(0.f, 0.f, 0.f, 0.f);
            g_score[r] = 0.0f;
            g_clsf[r] = 0.0f;
            continue;
        }
        unsigned int idx = ~(unsigned int)(key & 0xFFFFFFFFu);
        const float* row = pred + (size_t)idx * STRIDE;
        float x = row[0], y = row[1], w = row[2], h = row[3], obj = row[4];
        float bestv = -1.0f; int bestc = 0;
#pragma unroll 8
        for (int c = 0; c < NC; c++) {
            float p = __fmul_rn(row[5 + c], obj);
            if (p > bestv) { bestv = p; bestc = c; }
        }
        float hw = __fmul_rn(w, 0.5f), hh = __fmul_rn(h, 0.5f);
        float x1 = __fsub_rn(x, hw), y1 = __fsub_rn(y, hh);
        float x2 = __fadd_rn(x, hw), y2 = __fadd_rn(y, hh);
        float cf = (float)bestc;
        float off = __fmul_rn(cf, MAX_WH);
        float ox1 = __fadd_rn(x1, off), oy1 = __fadd_rn(y1, off);
        float ox2 = __fadd_rn(x2, off), oy2 = __fadd_rn(y2, off);
        float area = __fmul_rn(__fsub_rn(ox2, ox1), __fsub_rn(oy2, oy1));
        g_obox[r]  = make_float4(ox1, oy1, ox2, oy2);
        g_area[r]  = area;
        g_bbox[r]  = make_float4(x1, y1, x2, y2);
        g_score[r] = __uint_as_float(kb);
        g_clsf[r]  = cf;
    }
}

// ---------------- K5: 4096x4096 strict-upper suppression bitmask ----------------
__global__ void k_mask() {
    int cb = blockIdx.x, rb = blockIdx.y;
    if (cb < rb) return;                       // only upper-triangle word blocks
    __shared__ float4 cob[64];
    __shared__ float  car[64];
    int t = threadIdx.x;
    int col0 = cb * 64;
    cob[t] = g_obox[col0 + t];
    car[t] = g_area[col0 + t];
    __syncthreads();
    int row = rb * 64 + t;
    float4 a = g_obox[row];
    float  aa = g_area[row];
    unsigned long long bits = 0ULL;
#pragma unroll 8
    for (int k = 0; k < 64; k++) {
        int col = col0 + k;
        if (col > row) {
            float4 b = cob[k];
            float ltx = fmaxf(a.x, b.x), lty = fmaxf(a.y, b.y);
            float rbx = fminf(a.z, b.z), rby = fminf(a.w, b.w);
            float w = fmaxf(__fsub_rn(rbx, ltx), 0.0f);
            float h = fmaxf(__fsub_rn(rby, lty), 0.0f);
            float inter = __fmul_rn(w, h);
            float denom = __fadd_rn(__fsub_rn(__fadd_rn(aa, car[k]), inter), 1e-9f);
            float iou = __fdiv_rn(inter, denom);
            if (iou > IOU_T) bits |= (1ULL << k);
        }
    }
    g_mask[(size_t)row * 64 + cb] = bits;
}

// ---------------- K6: greedy reduce (64-chunked) + emit output ----------------
__global__ void k_final(float* __restrict__ out) {
    __shared__ unsigned long long remv[64];
    __shared__ unsigned long long diag[64];
    __shared__ int rowlist[64];
    __shared__ int s_n;
    __shared__ unsigned int pref[64];
    int tid = threadIdx.x;
    if (tid < 64) remv[tid] = g_remv[tid];
    __syncthreads();

    for (int c = 0; c < 64; c++) {
        if (tid < 64) diag[tid] = g_mask[(size_t)(c * 64 + tid) * 64 + c];
        __syncthreads();
        if (tid == 0) {
            unsigned long long rl = remv[c];
            int n = 0;
            for (int b = 0; b < 64; b++) {
                if (!((rl >> b) & 1ULL)) { rl |= diag[b]; rowlist[n++] = b; }
            }
            remv[c] = rl;
            s_n = n;
        }
        __syncthreads();
        int n = s_n;
        int w = tid >> 4, g = tid & 15;
        unsigned long long acc = 0ULL;
        if (w > c) {
            for (int q = g; q < n; q += 16)
                acc |= g_mask[(size_t)(c * 64 + rowlist[q]) * 64 + w];
        }
        acc |= __shfl_down_sync(0xffffffffu, acc, 8, 16);
        acc |= __shfl_down_sync(0xffffffffu, acc, 4, 16);
        acc |= __shfl_down_sync(0xffffffffu, acc, 2, 16);
        acc |= __shfl_down_sync(0xffffffffu, acc, 1, 16);
        if (g == 0 && w > c) remv[w] |= acc;
        __syncthreads();
    }

    // exclusive prefix of kept counts per word
    if (tid == 0) {
        unsigned int run = 0;
        for (int w = 0; w < 64; w++) { pref[w] = run; run += __popcll(~remv[w]); }
    }
    __syncthreads();
    // zero output, then scatter kept rows
    for (int j = tid; j < MAX_DET * 6; j += 1024) out[j] = 0.0f;
    __syncthreads();
    for (int i = tid; i < MAX_NMS; i += 1024) {
        unsigned long long wv = remv[i >> 6];
        int b = i & 63;
        if (!((wv >> b) & 1ULL)) {
            unsigned int rank = pref[i >> 6] +
                (unsigned int)__popcll((~wv) & ((1ULL << b) - 1ULL));
            if (rank < (unsigned)MAX_DET) {
                float4 bb = g_bbox[i];
                float* o = out + (size_t)rank * 6;
                o[0] = bb.x; o[1] = bb.y; o[2] = bb.z; o[3] = bb.w;
                o[4] = g_score[i]; o[5] = g_clsf[i];
            }
        }
    }
}

// ---------------- launch ----------------
extern "C" void kernel_launch(void* const* d_in, const int* in_sizes, int n_in,
                              void* d_out, int out_size) {
    const float* pred = (const float*)d_in[0];
    float* out = (float*)d_out;

    cudaFuncSetAttribute(k_sort, cudaFuncAttributeMaxDynamicSharedMemorySize,
                         CAP * (int)sizeof(unsigned long long));

    int nb = (N + 255) / 256;
    k_zero<<<(NBUCKET + 255) / 256, 256>>>();
    k_scores<<<nb, 256>>>(pred);
    k_cutoff<<<1, 1024>>>();
    k_gather<<<nb, 256>>>();
    k_sort<<<1, 1024, CAP * sizeof(unsigned long long)>>>(pred);
    k_mask<<<dim3(64, 64), 64>>>();
    k_final<<<1, 1024>>>(out);
}

// round 6
// speedup vs baseline: 2.1916x; 2.1916x over previous
#include <cuda_runtime.h>
#include <stdint.h>

#define N        100800
#define NC       80
#define STRIDE   85
#define MAX_NMS  4096
#define MAX_DET  1000
#define CAP      16384
#define NBUCKET  65536
#define CONF_T   0.4f
#define IOU_T    0.45f
#define MAX_WH   7680.0f
#define BS_MAX   4096

typedef unsigned long long u64;

// ---------------- scratch (static __device__, allocation-free) ----------------
__device__ unsigned int g_key[N];
__device__ unsigned int g_hist[NBUCKET];
__device__ unsigned int g_boff[NBUCKET];
__device__ unsigned int g_bcnt[NBUCKET];
__device__ unsigned int g_cutoff;
__device__ unsigned int g_bmax;
__device__ unsigned int g_total;
__device__ u64          g_cand[CAP];
__device__ float4       g_obox[MAX_NMS];
__device__ float        g_area[MAX_NMS];
__device__ float4       g_bbox[MAX_NMS];
__device__ float        g_score[MAX_NMS];
__device__ float        g_clsf[MAX_NMS];
__device__ u64          g_remv[64];
__device__ u64          g_rowany[MAX_NMS];        // bit w: mask[row][w] != 0
__device__ u64          g_mask[MAX_NMS * 64];

// ---------------- K0: zero scratch ----------------
__global__ void k_zero() {
    int i = blockIdx.x * blockDim.x + threadIdx.x;
    if (i < NBUCKET) g_hist[i] = 0u;
    if (i < MAX_NMS) g_rowany[i] = 0ULL;
    if (i < 64)      g_remv[i] = 0ULL;
}

// ---------------- K1: per-anchor conf + histogram ----------------
__global__ void k_scores(const float* __restrict__ pred) {
    int i = blockIdx.x * blockDim.x + threadIdx.x;
    if (i >= N) return;
    const float* r = pred + (size_t)i * STRIDE;
    float obj = r[4];
    float best = -1.0f;
#pragma unroll 8
    for (int c = 0; c < NC; c++) {
        float p = __fmul_rn(r[5 + c], obj);
        if (p > best) best = p;
    }
    unsigned int key = 0u;
    if (best > CONF_T) key = __float_as_uint(best);   // positive -> monotone bits
    g_key[i] = key;
    if (key) atomicAdd(&g_hist[key >> 16], 1u);
}

// ---------------- K2: suffix scan -> per-bucket offsets, cutoff, bmax, total ----
__global__ void k_scan() {
    __shared__ unsigned int ssum[1024];
    __shared__ unsigned int s_total;
    __shared__ int s_bmax;
    int t = threadIdx.x;
    int base = t * 64;
    unsigned int seg = 0;
#pragma unroll 8
    for (int k = 0; k < 64; k++) seg += g_hist[base + k];
    ssum[t] = seg;
    __syncthreads();
    for (int off = 1; off < 1024; off <<= 1) {   // inclusive suffix scan
        unsigned int v = (t + off < 1024) ? ssum[t + off] : 0u;
        __syncthreads();
        ssum[t] += v;
        __syncthreads();
    }
    if (t == 0) { s_total = ssum[0]; s_bmax = 0; }
    __syncthreads();

    unsigned int run = (t < 1023) ? ssum[t + 1] : 0u;
    int cross_b = -1;
    unsigned int cross_total = 0;
    int local_bmax = -1;
    for (int k = 63; k >= 0; k--) {
        unsigned int hb = g_hist[base + k];
        g_boff[base + k] = run;                  // items strictly above bucket
        g_bcnt[base + k] = 0u;
        unsigned int suf = run + hb;
        if (run < (unsigned)MAX_NMS && suf >= (unsigned)MAX_NMS) {
            cross_b = base + k; cross_total = suf;
        }
        if (hb && local_bmax < 0) local_bmax = base + k;
        run = suf;
    }
    if (local_bmax >= 0) atomicMax(&s_bmax, local_bmax);
    __syncthreads();
    if (cross_b >= 0) { g_cutoff = (unsigned)cross_b; g_total = cross_total; }
    if (t == 0) {
        g_bmax = (unsigned)s_bmax;
        if (s_total < (unsigned)MAX_NMS) { g_cutoff = 0u; g_total = s_total; }
    }
}

// ---------------- K3: scatter candidates into bucket segments ----------------
__global__ void k_gather() {
    int i = blockIdx.x * blockDim.x + threadIdx.x;
    if (i >= N) return;
    unsigned int key = g_key[i];
    if (!key) return;
    unsigned int b = key >> 16;
    if (b < g_cutoff) return;
    unsigned int pos = g_boff[b] + atomicAdd(&g_bcnt[b], 1u);
    if (pos < CAP)
        g_cand[pos] = ((u64)key << 32) | (unsigned int)(~(unsigned int)i);
}

// ---------------- K4: per-bucket bitonic sort (descending) ----------------
__global__ void k_bsort() {
    extern __shared__ u64 sb[];
    unsigned int cutoff = g_cutoff, bmax = g_bmax;
    unsigned int start = cutoff > 0x3ECCu ? cutoff : 0x3ECCu;   // conf>0.4 floor
    int tid = threadIdx.x;
    for (unsigned int b = start + blockIdx.x; b <= bmax; b += gridDim.x) {
        unsigned int L = g_hist[b];
        if (L <= 1) continue;
        unsigned int off = g_boff[b];
        if (off >= (unsigned)MAX_NMS) continue;     // entirely beyond top-4096
        if (L > BS_MAX) L = BS_MAX;
        unsigned int P = 2; while (P < L) P <<= 1;
        for (unsigned int j = tid; j < P; j += blockDim.x)
            sb[j] = (j < L) ? g_cand[off + j] : 0ULL;
        __syncthreads();
        for (unsigned int k = 2; k <= P; k <<= 1) {
            for (unsigned int j = k >> 1; j > 0; j >>= 1) {
                for (unsigned int p = tid; p < P / 2; p += blockDim.x) {
                    unsigned int i = ((p & ~(j - 1)) << 1) | (p & (j - 1));
                    u64 a = sb[i], c = sb[i + j];
                    bool sw = ((i & k) == 0) ? (a < c) : (a > c);   // descending
                    if (sw) { sb[i] = c; sb[i + j] = a; }
                }
                __syncthreads();
            }
        }
        for (unsigned int j = tid; j < L; j += blockDim.x) g_cand[off + j] = sb[j];
        __syncthreads();
    }
}

// ---------------- K5: decode top MAX_NMS ranks ----------------
__global__ void k_decode(const float* __restrict__ pred) {
    int r = blockIdx.x * blockDim.x + threadIdx.x;
    if (r >= MAX_NMS) return;
    unsigned int total = g_total;
    if (total > (unsigned)MAX_NMS) total = MAX_NMS;
    if ((unsigned)r >= total) {
        atomicOr(&g_remv[r >> 6], 1ULL << (r & 63));
        g_obox[r] = make_float4(1e30f, 1e30f, 1e30f, 1e30f);
        g_area[r] = 0.0f;
        g_bbox[r] = make_float4(0.f, 0.f, 0.f, 0.f);
        g_score[r] = 0.0f;
        g_clsf[r] = 0.0f;
        return;
    }
    u64 key = g_cand[r];
    unsigned int kb = (unsigned int)(key >> 32);
    unsigned int idx = ~(unsigned int)(key & 0xFFFFFFFFu);
    const float* row = pred + (size_t)idx * STRIDE;
    float x = row[0], y = row[1], w = row[2], h = row[3], obj = row[4];
    float bestv = -1.0f; int bestc = 0;
#pragma unroll 8
    for (int c = 0; c < NC; c++) {
        float p = __fmul_rn(row[5 + c], obj);
        if (p > bestv) { bestv = p; bestc = c; }
    }
    float hw = __fmul_rn(w, 0.5f), hh = __fmul_rn(h, 0.5f);
    float x1 = __fsub_rn(x, hw), y1 = __fsub_rn(y, hh);
    float x2 = __fadd_rn(x, hw), y2 = __fadd_rn(y, hh);
    float cf = (float)bestc;
    float off = __fmul_rn(cf, MAX_WH);
    float ox1 = __fadd_rn(x1, off), oy1 = __fadd_rn(y1, off);
    float ox2 = __fadd_rn(x2, off), oy2 = __fadd_rn(y2, off);
    float area = __fmul_rn(__fsub_rn(ox2, ox1), __fsub_rn(oy2, oy1));
    g_obox[r]  = make_float4(ox1, oy1, ox2, oy2);
    g_area[r]  = area;
    g_bbox[r]  = make_float4(x1, y1, x2, y2);
    g_score[r] = __uint_as_float(kb);
    g_clsf[r]  = cf;
}

// ---------------- K6: 4096x4096 strict-upper suppression bitmask ----------------
__global__ void k_mask() {
    int cb = blockIdx.x, rb = blockIdx.y;
    if (cb < rb) return;
    __shared__ float4 cob[64];
    __shared__ float  car[64];
    int t = threadIdx.x;
    int col0 = cb * 64;
    cob[t] = g_obox[col0 + t];
    car[t] = g_area[col0 + t];
    __syncthreads();
    int row = rb * 64 + t;
    float4 a = g_obox[row];
    float  aa = g_area[row];
    u64 bits = 0ULL;
#pragma unroll 8
    for (int k = 0; k < 64; k++) {
        int col = col0 + k;
        if (col > row) {
            float4 bbx = cob[k];
            float ltx = fmaxf(a.x, bbx.x), lty = fmaxf(a.y, bbx.y);
            float rbx = fminf(a.z, bbx.z), rby = fminf(a.w, bbx.w);
            float w = fmaxf(__fsub_rn(rbx, ltx), 0.0f);
            float h = fmaxf(__fsub_rn(rby, lty), 0.0f);
            float inter = __fmul_rn(w, h);
            float denom = __fadd_rn(__fsub_rn(__fadd_rn(aa, car[k]), inter), 1e-9f);
            float iou = __fdiv_rn(inter, denom);
            if (iou > IOU_T) bits |= (1ULL << k);
        }
    }
    g_mask[(size_t)row * 64 + cb] = bits;
    if (bits) atomicOr(&g_rowany[row], 1ULL << cb);
}

// ---------------- K7: sparse greedy reduce + emit output ----------------
__global__ void k_final(float* __restrict__ out) {
    extern __shared__ u64 dyn[];
    u64* sdiag = dyn;           // [4096]: sdiag[c*64+b] = mask[c*64+b][c]
    u64* srow  = dyn + 4096;    // [4096]: rowany per row
    __shared__ u64 remv[64];
    __shared__ unsigned int bal_sh[2];
    __shared__ unsigned int pref[64];
    int tid = threadIdx.x;      // 128 threads

    for (int i = tid; i < MAX_NMS; i += 128) {
        sdiag[i] = g_mask[(size_t)i * 64 + (i >> 6)];
        srow[i]  = g_rowany[i];
    }
    if (tid < 64) remv[tid] = g_remv[tid];
    __syncthreads();

    for (int c = 0; c < 64; c++) {
        // ---- intra-chunk greedy (iterate only rows with nonzero diag) ----
        bool hasdiag = (tid < 64) && (sdiag[c * 64 + tid] != 0ULL);
        unsigned int bal = __ballot_sync(0xffffffffu, hasdiag);
        if (tid == 0) bal_sh[0] = bal;
        if (tid == 32) bal_sh[1] = bal;
        __syncthreads();
        if (tid == 0) {
            u64 nz = (u64)bal_sh[0] | ((u64)bal_sh[1] << 32);
            u64 rl = remv[c];
            u64 mm = nz & ~rl;
            while (mm) {
                int b = __ffsll((long long)mm) - 1;
                mm &= mm - 1;
                if (!((rl >> b) & 1ULL)) {
                    rl |= sdiag[c * 64 + b];
                    mm &= ~rl;
                }
            }
            remv[c] = rl;
        }
        __syncthreads();
        // ---- cross-chunk OR (only kept rows with any word > c) ----
        u64 rl = remv[c];
        u64 later = (c < 63) ? (~0ULL << (c + 1)) : 0ULL;
        bool needs = (tid < 64) && !((rl >> tid) & 1ULL) &&
                     ((srow[c * 64 + tid] & later) != 0ULL);
        unsigned int bal2 = __ballot_sync(0xffffffffu, needs);
        if (tid == 0) bal_sh[0] = bal2;
        if (tid == 32) bal_sh[1] = bal2;
        __syncthreads();
        u64 rows = (u64)bal_sh[0] | ((u64)bal_sh[1] << 32);
        if (rows && tid < 64 && tid > c) {
            u64 acc = 0ULL;
            u64 rr = rows;
            while (rr) {
                int b = __ffsll((long long)rr) - 1;
                rr &= rr - 1;
                acc |= g_mask[(size_t)(c * 64 + b) * 64 + tid];
            }
            remv[tid] |= acc;
        }
        __syncthreads();
    }

    // ---- compact kept rows -> output ----
    if (tid == 0) {
        unsigned int run = 0;
        for (int w = 0; w < 64; w++) { pref[w] = run; run += __popcll(~remv[w]); }
    }
    __syncthreads();
    for (int j = tid; j < MAX_DET * 6; j += 128) out[j] = 0.0f;
    __syncthreads();
    for (int i = tid; i < MAX_NMS; i += 128) {
        u64 wv = remv[i >> 6];
        int b = i & 63;
        if (!((wv >> b) & 1ULL)) {
            unsigned int rank = pref[i >> 6] +
                (unsigned int)__popcll((~wv) & ((1ULL << b) - 1ULL));
            if (rank < (unsigned)MAX_DET) {
                float4 bb = g_bbox[i];
                float* o = out + (size_t)rank * 6;
                o[0] = bb.x; o[1] = bb.y; o[2] = bb.z; o[3] = bb.w;
                o[4] = g_score[i]; o[5] = g_clsf[i];
            }
        }
    }
}

// ---------------- launch ----------------
extern "C" void kernel_launch(void* const* d_in, const int* in_sizes, int n_in,
                              void* d_out, int out_size) {
    const float* pred = (const float*)d_in[0];
    float* out = (float*)d_out;

    cudaFuncSetAttribute(k_bsort, cudaFuncAttributeMaxDynamicSharedMemorySize,
                         BS_MAX * (int)sizeof(u64));
    cudaFuncSetAttribute(k_final, cudaFuncAttributeMaxDynamicSharedMemorySize,
                         2 * MAX_NMS * (int)sizeof(u64));

    int nb = (N + 255) / 256;
    k_zero  <<<(NBUCKET + 255) / 256, 256>>>();
    k_scores<<<nb, 256>>>(pred);
    k_scan  <<<1, 1024>>>();
    k_gather<<<nb, 256>>>();
    k_bsort <<<64, 256, BS_MAX * sizeof(u64)>>>();
    k_decode<<<MAX_NMS / 256, 256>>>(pred);
    k_mask  <<<dim3(64, 64), 64>>>();
    k_final <<<1, 128, 2 * MAX_NMS * sizeof(u64)>>>(out);
}

// round 7
// speedup vs baseline: 8.9132x; 4.0671x over previous
#include <cuda_runtime.h>
#include <stdint.h>

#define N        100800
#define NC       80
#define STRIDE   85
#define MAX_NMS  4096
#define MAX_DET  1000
#define CAP      16384
#define NB       256            // key>>16 in [0x3ECC, 0x3F80) -> 180 used buckets
#define KBASE    0x3ECCu
#define CONF_T   0.4f
#define IOU_T    0.45f
#define MAX_WH   7680.0f
#define BS_MAX   4096
#define ECAP     16384

typedef unsigned long long u64;

// ---------------- scratch (static __device__, allocation-free) ----------------
__device__ unsigned int g_hdr[NB + 1];   // [0..255] hist, [256] edge count
__device__ unsigned int g_key[N];
__device__ unsigned int g_boff[NB];
__device__ unsigned int g_bcnt[NB];
__device__ unsigned int g_cutoff;
__device__ unsigned int g_bmax;
__device__ unsigned int g_total;
__device__ u64          g_cand[CAP];
__device__ float4       g_obox[MAX_NMS];
__device__ float        g_area[MAX_NMS];
__device__ float4       g_bbox[MAX_NMS];
__device__ float        g_score[MAX_NMS];
__device__ float        g_clsf[MAX_NMS];
__device__ unsigned int g_edge[ECAP];

// ---------------- K1: warp-per-anchor conf + 256-bucket histogram ----------------
__global__ void k_scores(const float* __restrict__ pred) {
    int warp = (blockIdx.x * blockDim.x + threadIdx.x) >> 5;
    int lane = threadIdx.x & 31;
    if (warp >= N) return;
    const float* r = pred + (size_t)warp * STRIDE;
    float v0 = r[lane];
    float v1 = r[lane + 32];
    float v2 = (lane < 21) ? r[lane + 64] : 0.0f;
    float obj = __shfl_sync(0xffffffffu, v0, 4);
    float m = -1.0f;
    if (lane >= 5) m = __fmul_rn(v0, obj);
    m = fmaxf(m, __fmul_rn(v1, obj));
    if (lane < 21) m = fmaxf(m, __fmul_rn(v2, obj));
#pragma unroll
    for (int off = 16; off > 0; off >>= 1)
        m = fmaxf(m, __shfl_xor_sync(0xffffffffu, m, off));
    if (lane == 0) {
        unsigned int key = 0u;
        if (m > CONF_T) key = __float_as_uint(m);  // positive -> monotone bits
        g_key[warp] = key;
        if (key) {
            unsigned int b = (key >> 16) - KBASE;
            if (b > 255u) b = 255u;
            atomicAdd(&g_hdr[b], 1u);
        }
    }
}

// ---------------- K2: 256-bucket suffix scan -> offsets, cutoff, total, bmax ----
__global__ void k_scan() {
    __shared__ unsigned int s[NB];
    __shared__ int sb;
    int t = threadIdx.x;
    unsigned int h = g_hdr[t];
    s[t] = h;
    if (t == 0) sb = 0;
    __syncthreads();
    for (int off = 1; off < NB; off <<= 1) {   // inclusive suffix scan
        unsigned int v = (t + off < NB) ? s[t + off] : 0u;
        __syncthreads();
        s[t] += v;
        __syncthreads();
    }
    g_boff[t] = (t < NB - 1) ? s[t + 1] : 0u;  // items strictly above bucket t
    g_bcnt[t] = 0u;
    if (s[t] >= (unsigned)MAX_NMS && (t == NB - 1 || s[t + 1] < (unsigned)MAX_NMS)) {
        g_cutoff = (unsigned)t;
        g_total = s[t];
    }
    if (h) atomicMax(&sb, t);
    __syncthreads();
    if (t == 0) {
        g_bmax = (unsigned)sb;
        if (s[0] < (unsigned)MAX_NMS) { g_cutoff = 0u; g_total = s[0]; }
    }
}

// ---------------- K3: scatter candidates into bucket segments ----------------
__global__ void k_gather() {
    int i = blockIdx.x * blockDim.x + threadIdx.x;
    if (i >= N) return;
    unsigned int key = g_key[i];
    if (!key) return;
    unsigned int b = (key >> 16) - KBASE;
    if (b > 255u) b = 255u;
    if (b < g_cutoff) return;
    unsigned int pos = g_boff[b] + atomicAdd(&g_bcnt[b], 1u);
    if (pos < CAP)
        g_cand[pos] = ((u64)key << 32) | (unsigned int)(~(unsigned int)i);
}

// ---------------- K4: per-bucket bitonic sort (descending) ----------------
__global__ void k_bsort() {
    extern __shared__ u64 sbuf[];
    unsigned int cutoff = g_cutoff, bmax = g_bmax;
    int tid = threadIdx.x;
    for (unsigned int b = cutoff + blockIdx.x; b <= bmax; b += gridDim.x) {
        unsigned int L = g_hdr[b];
        if (L <= 1) continue;
        unsigned int off = g_boff[b];
        if (off >= (unsigned)MAX_NMS) continue;
        if (L > BS_MAX) L = BS_MAX;
        unsigned int P = 2; while (P < L) P <<= 1;
        for (unsigned int j = tid; j < P; j += blockDim.x)
            sbuf[j] = (j < L) ? g_cand[off + j] : 0ULL;
        __syncthreads();
        for (unsigned int k = 2; k <= P; k <<= 1) {
            for (unsigned int j = k >> 1; j > 0; j >>= 1) {
                for (unsigned int p = tid; p < P / 2; p += blockDim.x) {
                    unsigned int i = ((p & ~(j - 1)) << 1) | (p & (j - 1));
                    u64 a = sbuf[i], c = sbuf[i + j];
                    bool sw = ((i & k) == 0) ? (a < c) : (a > c);   // descending
                    if (sw) { sbuf[i] = c; sbuf[i + j] = a; }
                }
                __syncthreads();
            }
        }
        for (unsigned int j = tid; j < L; j += blockDim.x) g_cand[off + j] = sbuf[j];
        __syncthreads();
    }
}

// ---------------- K5: decode top MAX_NMS ranks ----------------
__global__ void k_decode(const float* __restrict__ pred) {
    int r = blockIdx.x * blockDim.x + threadIdx.x;
    if (r >= MAX_NMS) return;
    unsigned int total = g_total;
    if (total > (unsigned)MAX_NMS) total = MAX_NMS;
    if ((unsigned)r >= total) {
        g_obox[r] = make_float4(1e30f, 1e30f, 1e30f, 1e30f);
        g_area[r] = 0.0f;
        g_bbox[r] = make_float4(0.f, 0.f, 0.f, 0.f);
        g_score[r] = 0.0f;
        g_clsf[r] = 0.0f;
        return;
    }
    u64 key = g_cand[r];
    unsigned int kb = (unsigned int)(key >> 32);
    unsigned int idx = ~(unsigned int)(key & 0xFFFFFFFFu);
    const float* row = pred + (size_t)idx * STRIDE;
    float x = row[0], y = row[1], w = row[2], h = row[3], obj = row[4];
    float bestv = -1.0f; int bestc = 0;
#pragma unroll 8
    for (int c = 0; c < NC; c++) {
        float p = __fmul_rn(row[5 + c], obj);
        if (p > bestv) { bestv = p; bestc = c; }
    }
    float hw = __fmul_rn(w, 0.5f), hh = __fmul_rn(h, 0.5f);
    float x1 = __fsub_rn(x, hw), y1 = __fsub_rn(y, hh);
    float x2 = __fadd_rn(x, hw), y2 = __fadd_rn(y, hh);
    float cf = (float)bestc;
    float off = __fmul_rn(cf, MAX_WH);
    float ox1 = __fadd_rn(x1, off), oy1 = __fadd_rn(y1, off);
    float ox2 = __fadd_rn(x2, off), oy2 = __fadd_rn(y2, off);
    float area = __fmul_rn(__fsub_rn(ox2, ox1), __fsub_rn(oy2, oy1));
    g_obox[r]  = make_float4(ox1, oy1, ox2, oy2);
    g_area[r]  = area;
    g_bbox[r]  = make_float4(x1, y1, x2, y2);
    g_score[r] = __uint_as_float(kb);
    g_clsf[r]  = cf;
}

// ---------------- K6: sparse suppression edge list ----------------
__global__ void k_edges() {
    int cb = blockIdx.x, rb = blockIdx.y;
    if (cb < rb) return;
    __shared__ float4 cob[64];
    __shared__ float  car[64];
    int t = threadIdx.x;
    int col0 = cb * 64;
    cob[t] = g_obox[col0 + t];
    car[t] = g_area[col0 + t];
    __syncthreads();
    int row = rb * 64 + t;
    float4 a = g_obox[row];
    float  aa = g_area[row];
#pragma unroll 8
    for (int k = 0; k < 64; k++) {
        int col = col0 + k;
        if (col > row) {
            float4 bbx = cob[k];
            float ltx = fmaxf(a.x, bbx.x), lty = fmaxf(a.y, bbx.y);
            float rbx = fminf(a.z, bbx.z), rby = fminf(a.w, bbx.w);
            float w = fmaxf(__fsub_rn(rbx, ltx), 0.0f);
            float h = fmaxf(__fsub_rn(rby, lty), 0.0f);
            float inter = __fmul_rn(w, h);
            if (inter > 0.0f) {
                float denom = __fadd_rn(__fsub_rn(__fadd_rn(aa, car[k]), inter), 1e-9f);
                float iou = __fdiv_rn(inter, denom);
                if (iou > IOU_T) {
                    unsigned int p = atomicAdd(&g_hdr[NB], 1u);
                    if (p < ECAP)
                        g_edge[p] = ((unsigned int)row << 12) | (unsigned int)col;
                }
            }
        }
    }
}

// ---------------- K7: sort edges + sequential greedy + emit output ----------------
__global__ void k_final(float* __restrict__ out) {
    extern __shared__ unsigned int se[];       // ECAP u32
    __shared__ u64 keep[64];
    __shared__ unsigned int pref[64];
    int tid = threadIdx.x;                     // 256 threads
    unsigned int E = g_hdr[NB];
    if (E > ECAP) E = ECAP;
    unsigned int total = g_total;
    if (total > (unsigned)MAX_NMS) total = MAX_NMS;

    if (tid < 64) {
        unsigned int base = tid * 64u;
        u64 w;
        if (total >= base + 64u) w = ~0ULL;
        else if (total <= base)  w = 0ULL;
        else w = (1ULL << (total - base)) - 1ULL;
        keep[tid] = w;
    }

    unsigned int P = 1; while (P < E) P <<= 1;
    for (unsigned int i = tid; i < P; i += 256)
        se[i] = (i < E) ? g_edge[i] : 0xFFFFFFFFu;
    __syncthreads();

    if (E > 1) {
        for (unsigned int k = 2; k <= P; k <<= 1) {
            for (unsigned int j = k >> 1; j > 0; j >>= 1) {
                for (unsigned int p = tid; p < P / 2; p += 256) {
                    unsigned int i = ((p & ~(j - 1)) << 1) | (p & (j - 1));
                    unsigned int a = se[i], c = se[i + j];
                    bool sw = ((i & k) == 0) ? (a > c) : (a < c);   // ascending
                    if (sw) { se[i] = c; se[i + j] = a; }
                }
                __syncthreads();
            }
        }
    }

    // sequential greedy: edges ascending by src => exact fori_loop semantics
    if (tid == 0) {
        for (unsigned int e = 0; e < E; e++) {
            unsigned int k = se[e];
            unsigned int s = k >> 12, d = k & 4095u;
            if ((keep[s >> 6] >> (s & 63u)) & 1ULL)
                keep[d >> 6] &= ~(1ULL << (d & 63u));
        }
        unsigned int run = 0;
        for (int w = 0; w < 64; w++) { pref[w] = run; run += __popcll(keep[w]); }
    }
    __syncthreads();

    for (int j = tid; j < MAX_DET * 6; j += 256) out[j] = 0.0f;
    __syncthreads();
    for (int i = tid; i < MAX_NMS; i += 256) {
        u64 wv = keep[i >> 6];
        int b = i & 63;
        if ((wv >> b) & 1ULL) {
            unsigned int rank = pref[i >> 6] +
                (unsigned int)__popcll(wv & ((1ULL << b) - 1ULL));
            if (rank < (unsigned)MAX_DET) {
                float4 bb = g_bbox[i];
                float* o = out + (size_t)rank * 6;
                o[0] = bb.x; o[1] = bb.y; o[2] = bb.z; o[3] = bb.w;
                o[4] = g_score[i]; o[5] = g_clsf[i];
            }
        }
    }
}

// ---------------- launch ----------------
extern "C" void kernel_launch(void* const* d_in, const int* in_sizes, int n_in,
                              void* d_out, int out_size) {
    const float* pred = (const float*)d_in[0];
    float* out = (float*)d_out;

    cudaFuncSetAttribute(k_bsort, cudaFuncAttributeMaxDynamicSharedMemorySize,
                         BS_MAX * (int)sizeof(u64));
    cudaFuncSetAttribute(k_final, cudaFuncAttributeMaxDynamicSharedMemorySize,
                         ECAP * (int)sizeof(unsigned int));

    void* hdr_ptr = nullptr;
    cudaGetSymbolAddress(&hdr_ptr, g_hdr);
    cudaMemsetAsync(hdr_ptr, 0, (NB + 1) * sizeof(unsigned int));

    k_scores<<<(N * 32) / 256, 256>>>(pred);      // warp per anchor, 12600 blocks
    k_scan  <<<1, NB>>>();
    k_gather<<<(N + 255) / 256, 256>>>();
    k_bsort <<<64, 256, BS_MAX * sizeof(u64)>>>();
    k_decode<<<MAX_NMS / 256, 256>>>(pred);
    k_edges <<<dim3(64, 64), 64>>>();
    k_final <<<1, 256, ECAP * sizeof(unsigned int)>>>(out);
}

// round 8
// speedup vs baseline: 8.9419x; 1.0032x over previous
#include <cuda_runtime.h>
#include <stdint.h>

#define N        100800
#define NC       80
#define STRIDE   85
#define MAX_NMS  4096
#define MAX_DET  1000
#define CAP      16384
#define NB       256            // key>>16 in [0x3ECC, 0x3F80) -> 180 used buckets
#define KBASE    0x3ECCu
#define CONF_T   0.4f
#define IOU_T    0.45f
#define MAX_WH   7680.0f
#define BS_MAX   4096
#define ECAP     16384

typedef unsigned long long u64;

// ---------------- scratch (static __device__, allocation-free) ----------------
__device__ unsigned int g_hdr[NB + 1];   // [0..255] hist, [256] edge count
__device__ unsigned int g_key[N];
__device__ unsigned int g_boff[NB];
__device__ unsigned int g_bcnt[NB];
__device__ unsigned int g_cutoff;
__device__ unsigned int g_bmax;
__device__ unsigned int g_total;
__device__ u64          g_cand[CAP];
__device__ float4       g_obox[MAX_NMS];
__device__ float        g_area[MAX_NMS];
__device__ float4       g_bbox[MAX_NMS];
__device__ float        g_score[MAX_NMS];
__device__ float        g_clsf[MAX_NMS];
__device__ unsigned int g_edge[ECAP];

// ---------------- K1: warp-per-anchor conf + 256-bucket histogram ----------------
__global__ void k_scores(const float* __restrict__ pred) {
    int warp = (blockIdx.x * blockDim.x + threadIdx.x) >> 5;
    int lane = threadIdx.x & 31;
    if (warp >= N) return;
    const float* r = pred + (size_t)warp * STRIDE;
    float v0 = r[lane];
    float v1 = r[lane + 32];
    float v2 = (lane < 21) ? r[lane + 64] : 0.0f;
    float obj = __shfl_sync(0xffffffffu, v0, 4);
    float m = -1.0f;
    if (lane >= 5) m = __fmul_rn(v0, obj);
    m = fmaxf(m, __fmul_rn(v1, obj));
    if (lane < 21) m = fmaxf(m, __fmul_rn(v2, obj));
#pragma unroll
    for (int off = 16; off > 0; off >>= 1)
        m = fmaxf(m, __shfl_xor_sync(0xffffffffu, m, off));
    if (lane == 0) {
        unsigned int key = 0u;
        if (m > CONF_T) key = __float_as_uint(m);  // positive -> monotone bits
        g_key[warp] = key;
        if (key) {
            unsigned int b = (key >> 16) - KBASE;
            if (b > 255u) b = 255u;
            atomicAdd(&g_hdr[b], 1u);
        }
    }
}

// ---------------- K2: 256-bucket suffix scan -> offsets, cutoff, total, bmax ----
__global__ void k_scan() {
    __shared__ unsigned int s[NB];
    __shared__ int sb;
    int t = threadIdx.x;
    unsigned int h = g_hdr[t];
    s[t] = h;
    if (t == 0) sb = 0;
    __syncthreads();
    for (int off = 1; off < NB; off <<= 1) {   // inclusive suffix scan
        unsigned int v = (t + off < NB) ? s[t + off] : 0u;
        __syncthreads();
        s[t] += v;
        __syncthreads();
    }
    g_boff[t] = (t < NB - 1) ? s[t + 1] : 0u;  // items strictly above bucket t
    g_bcnt[t] = 0u;
    if (s[t] >= (unsigned)MAX_NMS && (t == NB - 1 || s[t + 1] < (unsigned)MAX_NMS)) {
        g_cutoff = (unsigned)t;
        g_total = s[t];
    }
    if (h) atomicMax(&sb, t);
    __syncthreads();
    if (t == 0) {
        g_bmax = (unsigned)sb;
        if (s[0] < (unsigned)MAX_NMS) { g_cutoff = 0u; g_total = s[0]; }
    }
}

// ---------------- K3: scatter candidates into bucket segments ----------------
__global__ void k_gather() {
    int i = blockIdx.x * blockDim.x + threadIdx.x;
    if (i >= N) return;
    unsigned int key = g_key[i];
    if (!key) return;
    unsigned int b = (key >> 16) - KBASE;
    if (b > 255u) b = 255u;
    if (b < g_cutoff) return;
    unsigned int pos = g_boff[b] + atomicAdd(&g_bcnt[b], 1u);
    if (pos < CAP)
        g_cand[pos] = ((u64)key << 32) | (unsigned int)(~(unsigned int)i);
}

// ---------------- K4: per-bucket bitonic sort (descending) ----------------
__global__ void k_bsort() {
    extern __shared__ u64 sbuf[];
    unsigned int cutoff = g_cutoff, bmax = g_bmax;
    int tid = threadIdx.x;
    for (unsigned int b = cutoff + blockIdx.x; b <= bmax; b += gridDim.x) {
        unsigned int L = g_hdr[b];
        if (L <= 1) continue;
        unsigned int off = g_boff[b];
        if (off >= (unsigned)MAX_NMS) continue;
        if (L > BS_MAX) L = BS_MAX;
        unsigned int P = 2; while (P < L) P <<= 1;
        for (unsigned int j = tid; j < P; j += blockDim.x)
            sbuf[j] = (j < L) ? g_cand[off + j] : 0ULL;
        __syncthreads();
        for (unsigned int k = 2; k <= P; k <<= 1) {
            for (unsigned int j = k >> 1; j > 0; j >>= 1) {
                for (unsigned int p = tid; p < P / 2; p += blockDim.x) {
                    unsigned int i = ((p & ~(j - 1)) << 1) | (p & (j - 1));
                    u64 a = sbuf[i], c = sbuf[i + j];
                    bool sw = ((i & k) == 0) ? (a < c) : (a > c);   // descending
                    if (sw) { sbuf[i] = c; sbuf[i + j] = a; }
                }
                __syncthreads();
            }
        }
        for (unsigned int j = tid; j < L; j += blockDim.x) g_cand[off + j] = sbuf[j];
        __syncthreads();
    }
}

// ---------------- K5: decode top MAX_NMS ranks ----------------
__global__ void k_decode(const float* __restrict__ pred) {
    int r = blockIdx.x * blockDim.x + threadIdx.x;
    if (r >= MAX_NMS) return;
    unsigned int total = g_total;
    if (total > (unsigned)MAX_NMS) total = MAX_NMS;
    if ((unsigned)r >= total) {
        g_obox[r] = make_float4(1e30f, 1e30f, 1e30f, 1e30f);
        g_area[r] = 0.0f;
        g_bbox[r] = make_float4(0.f, 0.f, 0.f, 0.f);
        g_score[r] = 0.0f;
        g_clsf[r] = 0.0f;
        return;
    }
    u64 key = g_cand[r];
    unsigned int kb = (unsigned int)(key >> 32);
    unsigned int idx = ~(unsigned int)(key & 0xFFFFFFFFu);
    const float* row = pred + (size_t)idx * STRIDE;
    float x = row[0], y = row[1], w = row[2], h = row[3], obj = row[4];
    float bestv = -1.0f; int bestc = 0;
#pragma unroll 8
    for (int c = 0; c < NC; c++) {
        float p = __fmul_rn(row[5 + c], obj);
        if (p > bestv) { bestv = p; bestc = c; }
    }
    float hw = __fmul_rn(w, 0.5f), hh = __fmul_rn(h, 0.5f);
    float x1 = __fsub_rn(x, hw), y1 = __fsub_rn(y, hh);
    float x2 = __fadd_rn(x, hw), y2 = __fadd_rn(y, hh);
    float cf = (float)bestc;
    float off = __fmul_rn(cf, MAX_WH);
    float ox1 = __fadd_rn(x1, off), oy1 = __fadd_rn(y1, off);
    float ox2 = __fadd_rn(x2, off), oy2 = __fadd_rn(y2, off);
    float area = __fmul_rn(__fsub_rn(ox2, ox1), __fsub_rn(oy2, oy1));
    g_obox[r]  = make_float4(ox1, oy1, ox2, oy2);
    g_area[r]  = area;
    g_bbox[r]  = make_float4(x1, y1, x2, y2);
    g_score[r] = __uint_as_float(kb);
    g_clsf[r]  = cf;
}

// ---------------- K6: sparse suppression edge list ----------------
__global__ void k_edges() {
    int cb = blockIdx.x, rb = blockIdx.y;
    if (cb < rb) return;
    __shared__ float4 cob[64];
    __shared__ float  car[64];
    int t = threadIdx.x;
    int col0 = cb * 64;
    cob[t] = g_obox[col0 + t];
    car[t] = g_area[col0 + t];
    __syncthreads();
    int row = rb * 64 + t;
    float4 a = g_obox[row];
    float  aa = g_area[row];
#pragma unroll 8
    for (int k = 0; k < 64; k++) {
        int col = col0 + k;
        if (col > row) {
            float4 bbx = cob[k];
            float ltx = fmaxf(a.x, bbx.x), lty = fmaxf(a.y, bbx.y);
            float rbx = fminf(a.z, bbx.z), rby = fminf(a.w, bbx.w);
            float w = fmaxf(__fsub_rn(rbx, ltx), 0.0f);
            float h = fmaxf(__fsub_rn(rby, lty), 0.0f);
            float inter = __fmul_rn(w, h);
            if (inter > 0.0f) {
                float denom = __fadd_rn(__fsub_rn(__fadd_rn(aa, car[k]), inter), 1e-9f);
                float iou = __fdiv_rn(inter, denom);
                if (iou > IOU_T) {
                    unsigned int p = atomicAdd(&g_hdr[NB], 1u);
                    if (p < ECAP)
                        g_edge[p] = ((unsigned int)row << 12) | (unsigned int)col;
                }
            }
        }
    }
}

// ---------------- K7: sort edges + sequential greedy + emit output ----------------
__global__ void k_final(float* __restrict__ out) {
    extern __shared__ unsigned int se[];       // ECAP u32
    __shared__ u64 keep[64];
    __shared__ unsigned int pref[64];
    int tid = threadIdx.x;                     // 256 threads
    unsigned int E = g_hdr[NB];
    if (E > ECAP) E = ECAP;
    unsigned int total = g_total;
    if (total > (unsigned)MAX_NMS) total = MAX_NMS;

    if (tid < 64) {
        unsigned int base = tid * 64u;
        u64 w;
        if (total >= base + 64u) w = ~0ULL;
        else if (total <= base)  w = 0ULL;
        else w = (1ULL << (total - base)) - 1ULL;
        keep[tid] = w;
    }

    unsigned int P = 1; while (P < E) P <<= 1;
    for (unsigned int i = tid; i < P; i += 256)
        se[i] = (i < E) ? g_edge[i] : 0xFFFFFFFFu;
    __syncthreads();

    if (E > 1) {
        for (unsigned int k = 2; k <= P; k <<= 1) {
            for (unsigned int j = k >> 1; j > 0; j >>= 1) {
                for (unsigned int p = tid; p < P / 2; p += 256) {
                    unsigned int i = ((p & ~(j - 1)) << 1) | (p & (j - 1));
                    unsigned int a = se[i], c = se[i + j];
                    bool sw = ((i & k) == 0) ? (a > c) : (a < c);   // ascending
                    if (sw) { se[i] = c; se[i + j] = a; }
                }
                __syncthreads();
            }
        }
    }

    // sequential greedy: edges ascending by src => exact fori_loop semantics
    if (tid == 0) {
        for (unsigned int e = 0; e < E; e++) {
            unsigned int k = se[e];
            unsigned int s = k >> 12, d = k & 4095u;
            if ((keep[s >> 6] >> (s & 63u)) & 1ULL)
                keep[d >> 6] &= ~(1ULL << (d & 63u));
        }
        unsigned int run = 0;
        for (int w = 0; w < 64; w++) { pref[w] = run; run += __popcll(keep[w]); }
    }
    __syncthreads();

    for (int j = tid; j < MAX_DET * 6; j += 256) out[j] = 0.0f;
    __syncthreads();
    for (int i = tid; i < MAX_NMS; i += 256) {
        u64 wv = keep[i >> 6];
        int b = i & 63;
        if ((wv >> b) & 1ULL) {
            unsigned int rank = pref[i >> 6] +
                (unsigned int)__popcll(wv & ((1ULL << b) - 1ULL));
            if (rank < (unsigned)MAX_DET) {
                float4 bb = g_bbox[i];
                float* o = out + (size_t)rank * 6;
                o[0] = bb.x; o[1] = bb.y; o[2] = bb.z; o[3] = bb.w;
                o[4] = g_score[i]; o[5] = g_clsf[i];
            }
        }
    }
}

// ---------------- launch ----------------
extern "C" void kernel_launch(void* const* d_in, const int* in_sizes, int n_in,
                              void* d_out, int out_size) {
    const float* pred = (const float*)d_in[0];
    float* out = (float*)d_out;

    cudaFuncSetAttribute(k_bsort, cudaFuncAttributeMaxDynamicSharedMemorySize,
                         BS_MAX * (int)sizeof(u64));
    cudaFuncSetAttribute(k_final, cudaFuncAttributeMaxDynamicSharedMemorySize,
                         ECAP * (int)sizeof(unsigned int));

    void* hdr_ptr = nullptr;
    cudaGetSymbolAddress(&hdr_ptr, g_hdr);
    cudaMemsetAsync(hdr_ptr, 0, (NB + 1) * sizeof(unsigned int));

    k_scores<<<(N * 32) / 256, 256>>>(pred);      // warp per anchor, 12600 blocks
    k_scan  <<<1, NB>>>();
    k_gather<<<(N + 255) / 256, 256>>>();
    k_bsort <<<64, 256, BS_MAX * sizeof(u64)>>>();
    k_decode<<<MAX_NMS / 256, 256>>>(pred);
    k_edges <<<dim3(64, 64), 64>>>();
    k_final <<<1, 256, ECAP * sizeof(unsigned int)>>>(out);
}